// round 1
// baseline (speedup 1.0000x reference)
#include <cuda_runtime.h>
#include <cuda_bf16.h>
#include <stdint.h>

// FuzzyPooling: 2x2 stride-2 pooling with fuzzy membership selection.
// x: (32,64,128,128) fp32 -> out: (32,64,64,64) fp32
//
// mu1 = tri(v, 1.5, 1.5); mu2 = tri(v, 3.0, 1.5); mu3 == mu2 (identical
// constants in the reference), and argmax takes the first max, so the
// selection collapses to: sel = (sum(mu1) >= sum(mu2)) ? mu1 : mu2.
// out = den==0 ? 0 : sum(mu*v*v)/sum(mu*v)

#define H_IN   128
#define W_IN   128
#define HO     64
#define WO     64
#define BC     (32 * 64)          // batch*channels planes
#define N_OUT  (BC * HO * WO)     // 8,388,608

__device__ __forceinline__ float tri_(float v, float c) {
    // width = 1.5 for both memberships
    const float inv_w = 1.0f / 1.5f;
    return fmaxf(1.0f - fabsf(v - c) * inv_w, 0.0f);
}

__device__ __forceinline__ float fuzzy_patch(float a, float b, float c, float d) {
    // memberships
    float m1a = tri_(a, 1.5f), m1b = tri_(b, 1.5f), m1c = tri_(c, 1.5f), m1d = tri_(d, 1.5f);
    float m2a = tri_(a, 3.0f), m2b = tri_(b, 3.0f), m2c = tri_(c, 3.0f), m2d = tri_(d, 3.0f);
    float s1 = (m1a + m1b) + (m1c + m1d);
    float s2 = (m2a + m2b) + (m2c + m2d);
    bool pick1 = (s1 >= s2);
    float ma = pick1 ? m1a : m2a;
    float mb = pick1 ? m1b : m2b;
    float mc = pick1 ? m1c : m2c;
    float md = pick1 ? m1d : m2d;
    float den = fmaf(ma, a, fmaf(mb, b, fmaf(mc, c, md * d)));
    float num = fmaf(ma * a, a, fmaf(mb * b, b, fmaf(mc * c, c, (md * d) * d)));
    return (den == 0.0f) ? 0.0f : num / den;
}

__global__ __launch_bounds__(256)
void fuzzy_pool_kernel(const float* __restrict__ x, float* __restrict__ out) {
    // Each thread computes 2 adjacent outputs (one float4 per input row).
    // total threads = N_OUT / 2
    int tid = blockIdx.x * blockDim.x + threadIdx.x;
    if (tid >= N_OUT / 2) return;

    int wp  = tid & 31;            // pair index along Wo (WO/2 = 32)
    int ho  = (tid >> 5) & 63;     // output row
    int bc  = tid >> 11;           // plane

    const float* base = x + (size_t)bc * (H_IN * W_IN) + (2 * ho) * W_IN + 4 * wp;
    float4 r0 = *reinterpret_cast<const float4*>(base);
    float4 r1 = *reinterpret_cast<const float4*>(base + W_IN);

    float o0 = fuzzy_patch(r0.x, r0.y, r1.x, r1.y);
    float o1 = fuzzy_patch(r0.z, r0.w, r1.z, r1.w);

    float2* op = reinterpret_cast<float2*>(out + (size_t)bc * (HO * WO) + ho * WO + 2 * wp);
    *op = make_float2(o0, o1);
}

extern "C" void kernel_launch(void* const* d_in, const int* in_sizes, int n_in,
                              void* d_out, int out_size) {
    const float* x = (const float*)d_in[0];
    float* out = (float*)d_out;
    int threads = 256;
    int total = N_OUT / 2;                 // 4,194,304
    int blocks = (total + threads - 1) / threads;   // 16384
    fuzzy_pool_kernel<<<blocks, threads>>>(x, out);
}

// round 2
// speedup vs baseline: 1.0724x; 1.0724x over previous
#include <cuda_runtime.h>
#include <cuda_bf16.h>
#include <stdint.h>

// FuzzyPooling: 2x2 stride-2 pooling with fuzzy membership selection.
// x: (32,64,128,128) fp32 -> out: (32,64,64,64) fp32
//
// mu1 = tri(v,1.5,1.5); mu2 = tri(v,3.0,1.5); mu3 == mu2, argmax picks
// first max -> sel = (sum(mu1) >= sum(mu2)) ? mu1 : mu2.
// out = den==0 ? 0 : sum(mu*v*v)/sum(mu*v)
//
// R2: 4 outputs/thread -> 4 independent float4 loads batched up front
// (MLP_p1=4), float4 store, streaming cache hints (.cs), amortized index math.

#define H_IN   128
#define W_IN   128
#define HO     64
#define WO     64
#define BC     (32 * 64)
#define N_OUT  (BC * HO * WO)     // 8,388,608

__device__ __forceinline__ float tri_(float v, float c) {
    const float inv_w = 1.0f / 1.5f;   // width = 1.5 for both memberships
    return fmaxf(1.0f - fabsf(v - c) * inv_w, 0.0f);
}

__device__ __forceinline__ float fuzzy_patch(float a, float b, float c, float d) {
    float m1a = tri_(a, 1.5f), m1b = tri_(b, 1.5f), m1c = tri_(c, 1.5f), m1d = tri_(d, 1.5f);
    float m2a = tri_(a, 3.0f), m2b = tri_(b, 3.0f), m2c = tri_(c, 3.0f), m2d = tri_(d, 3.0f);
    float s1 = (m1a + m1b) + (m1c + m1d);
    float s2 = (m2a + m2b) + (m2c + m2d);
    bool pick1 = (s1 >= s2);
    float ma = pick1 ? m1a : m2a;
    float mb = pick1 ? m1b : m2b;
    float mc = pick1 ? m1c : m2c;
    float md = pick1 ? m1d : m2d;
    float den = fmaf(ma, a, fmaf(mb, b, fmaf(mc, c, md * d)));
    float num = fmaf(ma * a, a, fmaf(mb * b, b, fmaf(mc * c, c, (md * d) * d)));
    return (den == 0.0f) ? 0.0f : num / den;
}

__global__ __launch_bounds__(256)
void fuzzy_pool_kernel(const float* __restrict__ x, float* __restrict__ out) {
    // Each thread computes 4 adjacent outputs: 8 input floats from each of
    // two rows = 4x float4 loads, issued back-to-back for MLP.
    int tid = blockIdx.x * blockDim.x + threadIdx.x;
    // total threads = N_OUT / 4 = 2,097,152; grid sized exactly, no bounds check

    int wq  = tid & 15;            // quad index along Wo (WO/4 = 16)
    int ho  = (tid >> 4) & 63;     // output row
    int bc  = tid >> 10;           // plane

    const float4* base0 = reinterpret_cast<const float4*>(
        x + (size_t)bc * (H_IN * W_IN) + (2 * ho) * W_IN + 8 * wq);
    const float4* base1 = base0 + (W_IN / 4);

    // 4 independent loads, all in flight before any compute (streaming hint)
    float4 a0 = __ldcs(base0);
    float4 a1 = __ldcs(base0 + 1);
    float4 b0 = __ldcs(base1);
    float4 b1 = __ldcs(base1 + 1);

    float4 o;
    o.x = fuzzy_patch(a0.x, a0.y, b0.x, b0.y);
    o.y = fuzzy_patch(a0.z, a0.w, b0.z, b0.w);
    o.z = fuzzy_patch(a1.x, a1.y, b1.x, b1.y);
    o.w = fuzzy_patch(a1.z, a1.w, b1.z, b1.w);

    __stcs(reinterpret_cast<float4*>(
        out + (size_t)bc * (HO * WO) + ho * WO + 4 * wq), o);
}

extern "C" void kernel_launch(void* const* d_in, const int* in_sizes, int n_in,
                              void* d_out, int out_size) {
    const float* x = (const float*)d_in[0];
    float* out = (float*)d_out;
    int threads = 256;
    int total = N_OUT / 4;                         // 2,097,152
    int blocks = total / threads;                  // 8192 exactly
    fuzzy_pool_kernel<<<blocks, threads>>>(x, out);
}